// round 9
// baseline (speedup 1.0000x reference)
#include <cuda_runtime.h>
#include <cuda_bf16.h>
#include <cstdint>

#define NN 64
#define CC 256
#define TT 64
#define VV 25
#define VP2 26
#define TVP (TT * VP2)            // 1664 padded cols = 13 x 128
#define NROWS (NN * CC * TT)      // 1,048,576 rows
#define ELEMS26 (NROWS * VP2)

typedef unsigned long long ull;

// Device scratch (no cudaMalloc allowed)
__device__ float g_r0[ELEMS26];                  // residual ping (padded 26)
__device__ float g_r1[ELEMS26];                  // residual pong (padded 26)
__device__ __nv_bfloat16 g_yhi[ELEMS26];         // mixed, bf16 hi (padded 26)
__device__ __nv_bfloat16 g_ylo[ELEMS26];         // mixed, bf16 lo (padded 26)
__device__ __nv_bfloat16 g_whi[4 * CC * CC];
__device__ __nv_bfloat16 g_wlo[4 * CC * CC];

// ---------------- PTX helpers ----------------
__device__ __forceinline__ uint32_t smem_u32(const void* p) {
    uint32_t a;
    asm("{ .reg .u64 t; cvta.to.shared.u64 t, %1; cvt.u32.u64 %0, t; }" : "=r"(a) : "l"(p));
    return a;
}
__device__ __forceinline__ ull ffma2(ull a, ull b, ull c) {
    ull d; asm("fma.rn.f32x2 %0, %1, %2, %3;" : "=l"(d) : "l"(a), "l"(b), "l"(c)); return d;
}
__device__ __forceinline__ ull pack2(float x) {
    ull d; unsigned xu = __float_as_uint(x);
    asm("mov.b64 %0, {%1, %2};" : "=l"(d) : "r"(xu), "r"(xu)); return d;
}
__device__ __forceinline__ ull pack2f(float lo, float hi) {
    ull d; asm("mov.b64 %0, {%1, %2};" : "=l"(d) : "r"(__float_as_uint(lo)), "r"(__float_as_uint(hi))); return d;
}
__device__ __forceinline__ float lo32(ull a) { return __uint_as_float((unsigned)(a & 0xffffffffULL)); }
__device__ __forceinline__ float hi32(ull a) { return __uint_as_float((unsigned)(a >> 32)); }

__device__ __forceinline__ void ldsm_x4(uint32_t* r, uint32_t addr) {
    asm volatile("ldmatrix.sync.aligned.m8n8.x4.shared.b16 {%0,%1,%2,%3}, [%4];"
                 : "=r"(r[0]), "=r"(r[1]), "=r"(r[2]), "=r"(r[3]) : "r"(addr));
}
__device__ __forceinline__ void ldsm_x4_t(uint32_t* r, uint32_t addr) {
    asm volatile("ldmatrix.sync.aligned.m8n8.x4.trans.shared.b16 {%0,%1,%2,%3}, [%4];"
                 : "=r"(r[0]), "=r"(r[1]), "=r"(r[2]), "=r"(r[3]) : "r"(addr));
}
__device__ __forceinline__ void mma_bf16(float* c, const uint32_t* a, const uint32_t* b) {
    asm volatile("mma.sync.aligned.m16n8k16.row.col.f32.bf16.bf16.f32 "
                 "{%0,%1,%2,%3}, {%4,%5,%6,%7}, {%8,%9}, {%0,%1,%2,%3};"
                 : "+f"(c[0]), "+f"(c[1]), "+f"(c[2]), "+f"(c[3])
                 : "r"(a[0]), "r"(a[1]), "r"(a[2]), "r"(a[3]), "r"(b[0]), "r"(b[1]));
}
__device__ __forceinline__ void cp16(uint32_t dst, const void* src) {
    asm volatile("cp.async.cg.shared.global [%0], [%1], 16;" :: "r"(dst), "l"(src) : "memory");
}
#define CP_COMMIT() asm volatile("cp.async.commit_group;" ::: "memory")

// ---------------- W split kernel (once, all 4 layers) ----------------
__global__ void __launch_bounds__(256)
wsplit_kernel(const float* __restrict__ w0, const float* __restrict__ w1,
              const float* __restrict__ w2, const float* __restrict__ w3,
              __nv_bfloat16* __restrict__ whi, __nv_bfloat16* __restrict__ wlo)
{
    int id = blockIdx.x * 256 + threadIdx.x;
    const float* ws[4] = { w0, w1, w2, w3 };
    float v = ws[id >> 16][id & 65535];
    __nv_bfloat16 h = __float2bfloat16_rn(v);
    whi[id] = h;
    wlo[id] = __float2bfloat16_rn(v - __bfloat162float(h));
}

// ---------------- Mix: y = A-mix(res), emit bf16 hi/lo padded-26 ----------------
// 256 threads, 256 rows/CTA. Input stride sin (25 for layer-0 x, else 26).
__global__ void __launch_bounds__(256)
mix_kernel(const float* __restrict__ in, const float* __restrict__ Amat,
           __nv_bfloat16* __restrict__ yhi, __nv_bfloat16* __restrict__ ylo,
           int sin)
{
    __shared__ float slab[6656];
    __shared__ ull sAp[325];
    const int tid = threadIdx.x;
    const int blk = blockIdx.x;

    for (int i = tid; i < 325; i += 256) {
        int u = i / 13, j = i - u * 13;
        float lo = Amat[(2 * j) * VV + u];
        float hi = (2 * j + 1 < VV) ? Amat[(2 * j + 1) * VV + u] : 0.f;
        sAp[i] = pack2f(lo, hi);
    }
    {
        const float4* src = (const float4*)(in + (size_t)blk * 256 * sin);
        const int n4 = (256 * sin) / 4;    // 1600 or 1664
        float4* dst = (float4*)slab;
        for (int i = tid; i < n4; i += 256) dst[i] = src[i];
    }
    __syncthreads();

    const int rb = tid * sin;
    float xr[VV];
#pragma unroll
    for (int u = 0; u < VV; u++) xr[u] = slab[rb + u];

    ull acc[13];
#pragma unroll
    for (int j = 0; j < 13; j++) acc[j] = 0ULL;
#pragma unroll
    for (int u = 0; u < VV; u++) {
        ull xu2 = pack2(xr[u]);
#pragma unroll
        for (int j = 0; j < 13; j++) acc[j] = ffma2(sAp[u * 13 + j], xu2, acc[j]);
    }
    __syncthreads();    // all input reads done before 26-stride overwrite

    const int ob = tid * VP2;
#pragma unroll
    for (int j = 0; j < 13; j++) {
        slab[ob + 2 * j]     = lo32(acc[j]);
        slab[ob + 2 * j + 1] = hi32(acc[j]);   // j==12: hi == 0 via A pad row
    }
    __syncthreads();

    // emit: 256 rows x 13 u32, coalesced
    uint32_t* yh32 = (uint32_t*)yhi + (size_t)blk * 3328;
    uint32_t* yl32 = (uint32_t*)ylo + (size_t)blk * 3328;
    for (int i = tid; i < 3328; i += 256) {
        int row = i / 13, j = i - row * 13;
        float v0 = slab[row * VP2 + 2 * j];
        float v1 = slab[row * VP2 + 2 * j + 1];
        __nv_bfloat16 h0 = __float2bfloat16_rn(v0);
        __nv_bfloat16 h1 = __float2bfloat16_rn(v1);
        __nv_bfloat16 l0 = __float2bfloat16_rn(v0 - __bfloat162float(h0));
        __nv_bfloat16 l1 = __float2bfloat16_rn(v1 - __bfloat162float(h1));
        __nv_bfloat162 hh; hh.x = h0; hh.y = h1;
        __nv_bfloat162 ll; ll.x = l0; ll.y = l1;
        yh32[i] = *(uint32_t*)&hh;
        yl32[i] = *(uint32_t*)&ll;
    }
}

// ---------------- GEMM: persistent-W, 3-stage Y pipeline, 3xBF16 mma ----------------
// grid (2, 64): x = mt (o/128), y = n. CTA loops over 13 column tiles of 128.
#define WS_STRIDE 80
#define YS_STRIDE 272
#define W_BYTES   163840                  // 2(hl) x 8(kc) x 128(o) x 80B
#define YST_BYTES 17408                   // hi 32x272 + lo 32x272
#define NSTAGE 3
#define SM_TOTAL (W_BYTES + NSTAGE * YST_BYTES)   // 216,064

__global__ void __launch_bounds__(256, 1)
gemm_kernel(const __nv_bfloat16* __restrict__ yhi, const __nv_bfloat16* __restrict__ ylo,
            const __nv_bfloat16* __restrict__ whi, const __nv_bfloat16* __restrict__ wlo,
            const float* __restrict__ bias, const float* __restrict__ res,
            float* __restrict__ out, int sr, int so)
{
    extern __shared__ __align__(16) unsigned char smem[];
    const uint32_t smu = smem_u32(smem);

    const int tid  = threadIdx.x;
    const int lane = tid & 31, wid = tid >> 5;
    const int wm   = wid >> 1, wn = wid & 1;     // 4 (M) x 2 (N)
    const int mt   = blockIdx.x;
    const int n    = blockIdx.y;

    const __nv_bfloat16* Wh = whi + (size_t)(mt * 128) * CC;
    const __nv_bfloat16* Wl = wlo + (size_t)(mt * 128) * CC;
    const __nv_bfloat16* Yh = yhi + (size_t)n * CC * TVP;
    const __nv_bfloat16* Yl = ylo + (size_t)n * CC * TVP;

    // ---- load persistent W: 8192 cp16 ----
    for (int idx = tid; idx < 8192; idx += 256) {
        const int hl = idx >> 12;
        const int kc = (idx >> 9) & 7;
        const int o  = (idx >> 2) & 127;
        const int p  = idx & 3;
        const __nv_bfloat16* src = (hl ? Wl : Wh) + (size_t)o * CC + kc * 32 + p * 8;
        cp16(smu + hl * 81920 + kc * 10240 + o * WS_STRIDE + p * 16, src);
    }

    // Y chunk issue: chunk q = ct*8 + kc -> stage q % 3 (1024 cp16, 4/thread)
    auto issueY = [&](int q) {
        const int ct = q >> 3, kc = q & 7;
        const int c0 = kc * 32;
        const int col0 = ct * 128;
        const uint32_t sb = smu + W_BYTES + (q % NSTAGE) * YST_BYTES;
#pragma unroll
        for (int r = 0; r < 2; r++) {
            const int qq = tid + r * 256;
            const int c = qq >> 4, g16 = qq & 15;
            const size_t src = (size_t)(c0 + c) * TVP + col0 + g16 * 8;
            const uint32_t dst = sb + c * YS_STRIDE + g16 * 16;
            cp16(dst,        Yh + src);
            cp16(dst + 8704, Yl + src);
        }
    };

    issueY(0); CP_COMMIT();
    issueY(1); CP_COMMIT();

    float acc[2][8][4];
#pragma unroll
    for (int fm = 0; fm < 2; fm++)
#pragma unroll
        for (int nb = 0; nb < 8; nb++)
#pragma unroll
            for (int qq = 0; qq < 4; qq++) acc[fm][nb][qq] = 0.f;

    const int g = lane >> 2, tig = lane & 3;

    for (int q = 0; q < 104; q++) {
        const int kc = q & 7;
        if (q + 2 < 104) {
            issueY(q + 2); CP_COMMIT();
            asm volatile("cp.async.wait_group 2;" ::: "memory");
        } else if (q + 1 < 104) {
            asm volatile("cp.async.wait_group 1;" ::: "memory");
        } else {
            asm volatile("cp.async.wait_group 0;" ::: "memory");
        }
        __syncthreads();

        const uint32_t swh = smu + kc * 10240;
        const uint32_t swl = smu + 81920 + kc * 10240;
        const uint32_t sy  = smu + W_BYTES + (q % NSTAGE) * YST_BYTES;

#pragma unroll
        for (int s = 0; s < 2; s++) {
            uint32_t Ah[2][4], Al[2][4];
            const uint32_t aoff = (uint32_t)(lane & 15) * WS_STRIDE + s * 32 + (lane >> 4) * 16;
            ldsm_x4(Ah[0], swh + (wm * 32 +  0) * WS_STRIDE + aoff);
            ldsm_x4(Ah[1], swh + (wm * 32 + 16) * WS_STRIDE + aoff);
            ldsm_x4(Al[0], swl + (wm * 32 +  0) * WS_STRIDE + aoff);
            ldsm_x4(Al[1], swl + (wm * 32 + 16) * WS_STRIDE + aoff);

            const uint32_t boff = (uint32_t)(s * 16 + (lane & 15)) * YS_STRIDE + (lane >> 4) * 16;
#pragma unroll
            for (int nbp = 0; nbp < 4; nbp++) {
                uint32_t Bh[4], Bl[4];
                const uint32_t bcol = (uint32_t)(wn * 64 + nbp * 16) * 2;
                ldsm_x4_t(Bh, sy + boff + bcol);
                ldsm_x4_t(Bl, sy + 8704 + boff + bcol);
#pragma unroll
                for (int h = 0; h < 2; h++) {
                    const int nb = nbp * 2 + h;
                    mma_bf16(acc[0][nb], Ah[0], &Bh[2 * h]);
                    mma_bf16(acc[0][nb], Ah[0], &Bl[2 * h]);
                    mma_bf16(acc[0][nb], Al[0], &Bh[2 * h]);
                    mma_bf16(acc[1][nb], Ah[1], &Bh[2 * h]);
                    mma_bf16(acc[1][nb], Ah[1], &Bl[2 * h]);
                    mma_bf16(acc[1][nb], Al[1], &Bh[2 * h]);
                }
            }
        }
        __syncthreads();

        if (kc == 7) {
            // ---- epilogue for column tile ct ----
            const int ct = q >> 3;
            const int col0 = ct * 128;
#pragma unroll
            for (int fm = 0; fm < 2; fm++) {
                const int o0 = mt * 128 + wm * 32 + fm * 16 + g;
                const float b0 = bias[o0];
                const float b1 = bias[o0 + 8];
                const size_t rb0 = ((size_t)n * CC + o0) * TT;       // row-time base
                const size_t rb1 = rb0 + 8 * TT;
#pragma unroll
                for (int nb = 0; nb < 8; nb++) {
                    const int jb = col0 + wn * 64 + nb * 8 + 2 * tig;
#pragma unroll
                    for (int e = 0; e < 2; e++) {
                        const int j = jb + e;
                        const int t = j / VP2;
                        const int v = j - t * VP2;
                        if (v < VV) {
                            float r0 = res[(rb0 + t) * sr + v];
                            out[(rb0 + t) * so + v] =
                                fmaxf(acc[fm][nb][e] + b0 + r0, 0.f);
                            float r1 = res[(rb1 + t) * sr + v];
                            out[(rb1 + t) * so + v] =
                                fmaxf(acc[fm][nb][2 + e] + b1 + r1, 0.f);
                        }
                    }
                    acc[fm][nb][0] = 0.f; acc[fm][nb][1] = 0.f;
                    acc[fm][nb][2] = 0.f; acc[fm][nb][3] = 0.f;
                }
            }
        }
    }
}

// ---------------- launch ----------------
extern "C" void kernel_launch(void* const* d_in, const int* in_sizes, int n_in,
                              void* d_out, int out_size)
{
    // metadata order: t, x, A, w1, b1, w2, b2, w3, b3, w4, b4
    const float* x  = (const float*)d_in[1];
    const float* A  = (const float*)d_in[2];
    const float* W[4] = { (const float*)d_in[3], (const float*)d_in[5],
                          (const float*)d_in[7], (const float*)d_in[9] };
    const float* B[4] = { (const float*)d_in[4], (const float*)d_in[6],
                          (const float*)d_in[8], (const float*)d_in[10] };
    float* out = (float*)d_out;

    float *r0, *r1;
    __nv_bfloat16 *yhi, *ylo, *whi, *wlo;
    cudaGetSymbolAddress((void**)&r0,  g_r0);
    cudaGetSymbolAddress((void**)&r1,  g_r1);
    cudaGetSymbolAddress((void**)&yhi, g_yhi);
    cudaGetSymbolAddress((void**)&ylo, g_ylo);
    cudaGetSymbolAddress((void**)&whi, g_whi);
    cudaGetSymbolAddress((void**)&wlo, g_wlo);

    cudaFuncSetAttribute(gemm_kernel,
                         cudaFuncAttributeMaxDynamicSharedMemorySize, SM_TOTAL);

    wsplit_kernel<<<1024, 256>>>(W[0], W[1], W[2], W[3], whi, wlo);

    dim3 ggrid(2, NN);
    const float* cur = x;       int curs = 25;
    float* nxt[4]   = { r0, r1, r0, out };
    int    nxts[4]  = { 26, 26, 26, 25 };

    for (int l = 0; l < 4; l++) {
        mix_kernel<<<NROWS / 256, 256>>>(cur, A, yhi, ylo, curs);
        gemm_kernel<<<ggrid, 256, SM_TOTAL>>>(yhi, ylo,
                                              whi + (size_t)l * CC * CC,
                                              wlo + (size_t)l * CC * CC,
                                              B[l], cur, nxt[l], curs, nxts[l]);
        cur = nxt[l]; curs = nxts[l];
    }
}

// round 10
// speedup vs baseline: 1.6168x; 1.6168x over previous
#include <cuda_runtime.h>
#include <cuda_bf16.h>
#include <cstdint>

#define NN 64
#define CC 256
#define TT 64
#define VV 25
#define VP2 26
#define TVP (TT * VP2)            // 1664 padded cols = 13 x 128
#define NROWS (NN * CC * TT)
#define ELEMS26 (NROWS * VP2)

typedef unsigned long long ull;

// Device scratch (no cudaMalloc allowed)
__device__ float g_r0[ELEMS26];                  // residual ping (padded 26)
__device__ float g_r1[ELEMS26];                  // residual pong (padded 26)
__device__ __nv_bfloat16 g_yhi[ELEMS26];         // mixed, bf16 hi (padded 26)
__device__ __nv_bfloat16 g_ylo[ELEMS26];         // mixed, bf16 lo (padded 26)
__device__ __nv_bfloat16 g_whi[4 * CC * CC];
__device__ __nv_bfloat16 g_wlo[4 * CC * CC];

// ---------------- PTX helpers ----------------
__device__ __forceinline__ uint32_t smem_u32(const void* p) {
    uint32_t a;
    asm("{ .reg .u64 t; cvta.to.shared.u64 t, %1; cvt.u32.u64 %0, t; }" : "=r"(a) : "l"(p));
    return a;
}
__device__ __forceinline__ ull ffma2(ull a, ull b, ull c) {
    ull d; asm("fma.rn.f32x2 %0, %1, %2, %3;" : "=l"(d) : "l"(a), "l"(b), "l"(c)); return d;
}
__device__ __forceinline__ ull pack2(float x) {
    ull d; unsigned xu = __float_as_uint(x);
    asm("mov.b64 %0, {%1, %2};" : "=l"(d) : "r"(xu), "r"(xu)); return d;
}
__device__ __forceinline__ ull pack2f(float lo, float hi) {
    ull d; asm("mov.b64 %0, {%1, %2};" : "=l"(d) : "r"(__float_as_uint(lo)), "r"(__float_as_uint(hi))); return d;
}
__device__ __forceinline__ float lo32(ull a) { return __uint_as_float((unsigned)(a & 0xffffffffULL)); }
__device__ __forceinline__ float hi32(ull a) { return __uint_as_float((unsigned)(a >> 32)); }

__device__ __forceinline__ void ldsm_x4(uint32_t* r, uint32_t addr) {
    asm volatile("ldmatrix.sync.aligned.m8n8.x4.shared.b16 {%0,%1,%2,%3}, [%4];"
                 : "=r"(r[0]), "=r"(r[1]), "=r"(r[2]), "=r"(r[3]) : "r"(addr));
}
__device__ __forceinline__ void ldsm_x4_t(uint32_t* r, uint32_t addr) {
    asm volatile("ldmatrix.sync.aligned.m8n8.x4.trans.shared.b16 {%0,%1,%2,%3}, [%4];"
                 : "=r"(r[0]), "=r"(r[1]), "=r"(r[2]), "=r"(r[3]) : "r"(addr));
}
__device__ __forceinline__ void mma_bf16(float* c, const uint32_t* a, const uint32_t* b) {
    asm volatile("mma.sync.aligned.m16n8k16.row.col.f32.bf16.bf16.f32 "
                 "{%0,%1,%2,%3}, {%4,%5,%6,%7}, {%8,%9}, {%0,%1,%2,%3};"
                 : "+f"(c[0]), "+f"(c[1]), "+f"(c[2]), "+f"(c[3])
                 : "r"(a[0]), "r"(a[1]), "r"(a[2]), "r"(a[3]), "r"(b[0]), "r"(b[1]));
}
__device__ __forceinline__ void cp16(uint32_t dst, const void* src) {
    asm volatile("cp.async.cg.shared.global [%0], [%1], 16;" :: "r"(dst), "l"(src) : "memory");
}
#define CP_COMMIT() asm volatile("cp.async.commit_group;" ::: "memory")

// ---------------- W split kernel (once, all 4 layers) ----------------
__global__ void __launch_bounds__(256)
wsplit_kernel(const float* __restrict__ w0, const float* __restrict__ w1,
              const float* __restrict__ w2, const float* __restrict__ w3,
              __nv_bfloat16* __restrict__ whi, __nv_bfloat16* __restrict__ wlo)
{
    int id = blockIdx.x * 256 + threadIdx.x;
    const float* ws[4] = { w0, w1, w2, w3 };
    float v = ws[id >> 16][id & 65535];
    __nv_bfloat16 h = __float2bfloat16_rn(v);
    whi[id] = h;
    wlo[id] = __float2bfloat16_rn(v - __bfloat162float(h));
}

// ---------------- Mix: y = A-mix(res), emit bf16 hi/lo padded-26 ----------------
// 256 threads, 256 rows/CTA. Input stride sin (25 for layer-0 x, else 26).
__global__ void __launch_bounds__(256)
mix_kernel(const float* __restrict__ in, const float* __restrict__ Amat,
           __nv_bfloat16* __restrict__ yhi, __nv_bfloat16* __restrict__ ylo,
           int sin)
{
    __shared__ float slab[6656];
    __shared__ ull sAp[325];
    const int tid = threadIdx.x;
    const int blk = blockIdx.x;

    for (int i = tid; i < 325; i += 256) {
        int u = i / 13, j = i - u * 13;
        float lo = Amat[(2 * j) * VV + u];
        float hi = (2 * j + 1 < VV) ? Amat[(2 * j + 1) * VV + u] : 0.f;
        sAp[i] = pack2f(lo, hi);
    }
    {
        const float4* src = (const float4*)(in + (size_t)blk * 256 * sin);
        const int n4 = (256 * sin) / 4;
        float4* dst = (float4*)slab;
        for (int i = tid; i < n4; i += 256) dst[i] = src[i];
    }
    __syncthreads();

    const int rb = tid * sin;
    float xr[VV];
#pragma unroll
    for (int u = 0; u < VV; u++) xr[u] = slab[rb + u];

    ull acc[13];
#pragma unroll
    for (int j = 0; j < 13; j++) acc[j] = 0ULL;
#pragma unroll
    for (int u = 0; u < VV; u++) {
        ull xu2 = pack2(xr[u]);
#pragma unroll
        for (int j = 0; j < 13; j++) acc[j] = ffma2(sAp[u * 13 + j], xu2, acc[j]);
    }
    __syncthreads();

    const int ob = tid * VP2;
#pragma unroll
    for (int j = 0; j < 13; j++) {
        slab[ob + 2 * j]     = lo32(acc[j]);
        slab[ob + 2 * j + 1] = hi32(acc[j]);   // j==12: hi == 0 via A pad row
    }
    __syncthreads();

    uint32_t* yh32 = (uint32_t*)yhi + (size_t)blk * 3328;
    uint32_t* yl32 = (uint32_t*)ylo + (size_t)blk * 3328;
    for (int i = tid; i < 3328; i += 256) {
        int row = i / 13, j = i - row * 13;
        float v0 = slab[row * VP2 + 2 * j];
        float v1 = slab[row * VP2 + 2 * j + 1];
        __nv_bfloat16 h0 = __float2bfloat16_rn(v0);
        __nv_bfloat16 h1 = __float2bfloat16_rn(v1);
        __nv_bfloat16 l0 = __float2bfloat16_rn(v0 - __bfloat162float(h0));
        __nv_bfloat16 l1 = __float2bfloat16_rn(v1 - __bfloat162float(h1));
        __nv_bfloat162 hh; hh.x = h0; hh.y = h1;
        __nv_bfloat162 ll; ll.x = l0; ll.y = l1;
        yh32[i] = *(uint32_t*)&hh;
        yl32[i] = *(uint32_t*)&ll;
    }
}

// ---------------- GEMM: out = relu(W @ y + b + res), 3xBF16 mma.sync ----------------
// grid (13, 2, 64): x = 128-col tile (exact, padded), y = M-tile (o/128), z = n
#define WS_STRIDE 80
#define YS_STRIDE 272
#define SM_WH 0
#define SM_WL 10240
#define SM_YH 20480
#define SM_YL 29184
#define STAGE_BYTES 37888
#define SM_TOTAL (2 * STAGE_BYTES)   // 75776

__global__ void __launch_bounds__(256, 2)
gemm_kernel(const __nv_bfloat16* __restrict__ yhi, const __nv_bfloat16* __restrict__ ylo,
            const __nv_bfloat16* __restrict__ whi, const __nv_bfloat16* __restrict__ wlo,
            const float* __restrict__ bias, const float* __restrict__ res,
            float* __restrict__ out, int sr, int so)
{
    extern __shared__ __align__(16) unsigned char smem[];
    const uint32_t smu = smem_u32(smem);

    const int tid  = threadIdx.x;
    const int lane = tid & 31, wid = tid >> 5;
    const int wm   = wid >> 1, wn = wid & 1;       // 4 (M) x 2 (N)
    const int ct   = blockIdx.x;
    const int mt   = blockIdx.y;
    const int n    = blockIdx.z;
    const int col0 = ct * 128;

    const __nv_bfloat16* Wh = whi + (size_t)(mt * 128) * CC;
    const __nv_bfloat16* Wl = wlo + (size_t)(mt * 128) * CC;
    const __nv_bfloat16* Yh = yhi + (size_t)n * CC * TVP + col0;
    const __nv_bfloat16* Yl = ylo + (size_t)n * CC * TVP + col0;

    auto issue = [&](int kc, int stg) {
        const int c0 = kc * 32;
        const uint32_t sbase = smu + stg * STAGE_BYTES;
#pragma unroll
        for (int r = 0; r < 2; r++) {
            const int q = tid + r * 256;
            const int o = q >> 2, cp4 = q & 3;
            const size_t wsrc = (size_t)o * CC + c0 + cp4 * 8;
            const uint32_t wdst = sbase + o * WS_STRIDE + cp4 * 16;
            cp16(wdst + SM_WH, Wh + wsrc);
            cp16(wdst + SM_WL, Wl + wsrc);
            const int c = q >> 4, jp = q & 15;
            const size_t ysrc = (size_t)(c0 + c) * TVP + jp * 8;
            const uint32_t ydst = sbase + c * YS_STRIDE + jp * 16;
            cp16(ydst + SM_YH, Yh + ysrc);
            cp16(ydst + SM_YL, Yl + ysrc);
        }
    };

    float acc[2][8][4];
#pragma unroll
    for (int fm = 0; fm < 2; fm++)
#pragma unroll
        for (int nb = 0; nb < 8; nb++)
#pragma unroll
            for (int q = 0; q < 4; q++) acc[fm][nb][q] = 0.f;

    issue(0, 0);
    CP_COMMIT();

    for (int kc = 0; kc < 8; kc++) {
        if (kc < 7) {
            issue(kc + 1, (kc + 1) & 1);
            CP_COMMIT();
            asm volatile("cp.async.wait_group 1;" ::: "memory");
        } else {
            asm volatile("cp.async.wait_group 0;" ::: "memory");
        }
        __syncthreads();

        const uint32_t st  = (kc & 1) ? STAGE_BYTES : 0u;
        const uint32_t swh = smu + st + SM_WH;
        const uint32_t swl = smu + st + SM_WL;
        const uint32_t syh = smu + st + SM_YH;
        const uint32_t syl = smu + st + SM_YL;

#pragma unroll
        for (int s = 0; s < 2; s++) {
            uint32_t Ah[2][4], Al[2][4];
            const uint32_t aoff = (uint32_t)(lane & 15) * WS_STRIDE + s * 32 + (lane >> 4) * 16;
            ldsm_x4(Ah[0], swh + (wm * 32 +  0) * WS_STRIDE + aoff);
            ldsm_x4(Ah[1], swh + (wm * 32 + 16) * WS_STRIDE + aoff);
            ldsm_x4(Al[0], swl + (wm * 32 +  0) * WS_STRIDE + aoff);
            ldsm_x4(Al[1], swl + (wm * 32 + 16) * WS_STRIDE + aoff);

            const uint32_t boff = (uint32_t)(s * 16 + (lane & 15)) * YS_STRIDE + (lane >> 4) * 16;
#pragma unroll
            for (int nbp = 0; nbp < 4; nbp++) {
                uint32_t Bh[4], Bl[4];
                const uint32_t bcol = (uint32_t)(wn * 64 + nbp * 16) * 2;
                ldsm_x4_t(Bh, syh + boff + bcol);
                ldsm_x4_t(Bl, syl + boff + bcol);
#pragma unroll
                for (int h = 0; h < 2; h++) {
                    const int nb = nbp * 2 + h;
                    mma_bf16(acc[0][nb], Ah[0], &Bh[2 * h]);
                    mma_bf16(acc[0][nb], Ah[0], &Bl[2 * h]);
                    mma_bf16(acc[0][nb], Al[0], &Bh[2 * h]);
                    mma_bf16(acc[1][nb], Ah[1], &Bh[2 * h]);
                    mma_bf16(acc[1][nb], Ah[1], &Bl[2 * h]);
                    mma_bf16(acc[1][nb], Al[1], &Bh[2 * h]);
                }
            }
        }
        __syncthreads();
    }

    // ---- epilogue: relu(acc + b[o] + res) ----
    const int g = lane >> 2, tig = lane & 3;
    const bool vr = (sr == VP2), vo = (so == VP2);

    auto epi2 = [&](int orow, int j, float a0, float a1, float bs) {
        const size_t rowb = (size_t)n * CC + orow;
        float r0v, r1v;
        if (vr) {
            float2 rr = *(const float2*)(res + rowb * TVP + j);
            r0v = rr.x; r1v = rr.y;
        } else {
            int t0 = j / VP2, v0 = j - t0 * VP2;
            int t1 = (j + 1) / VP2, v1 = (j + 1) - t1 * VP2;
            r0v = (v0 < VV) ? res[(rowb * TT + t0) * VV + v0] : 0.f;
            r1v = (v1 < VV) ? res[(rowb * TT + t1) * VV + v1] : 0.f;
        }
        float o0v = fmaxf(a0 + bs + r0v, 0.f);
        float o1v = fmaxf(a1 + bs + r1v, 0.f);
        if (vo) {
            *(float2*)(out + rowb * TVP + j) = make_float2(o0v, o1v);
        } else {
            int t0 = j / VP2, v0 = j - t0 * VP2;
            int t1 = (j + 1) / VP2, v1 = (j + 1) - t1 * VP2;
            if (v0 < VV) out[(rowb * TT + t0) * VV + v0] = o0v;
            if (v1 < VV) out[(rowb * TT + t1) * VV + v1] = o1v;
        }
    };

#pragma unroll
    for (int fm = 0; fm < 2; fm++) {
        const int o0 = mt * 128 + wm * 32 + fm * 16 + g;
        const float b0 = bias[o0];
        const float b1 = bias[o0 + 8];
#pragma unroll
        for (int nb = 0; nb < 8; nb++) {
            const int j = col0 + wn * 64 + nb * 8 + 2 * tig;
            epi2(o0,     j, acc[fm][nb][0], acc[fm][nb][1], b0);
            epi2(o0 + 8, j, acc[fm][nb][2], acc[fm][nb][3], b1);
        }
    }
}

// ---------------- launch ----------------
extern "C" void kernel_launch(void* const* d_in, const int* in_sizes, int n_in,
                              void* d_out, int out_size)
{
    // metadata order: t, x, A, w1, b1, w2, b2, w3, b3, w4, b4
    const float* x  = (const float*)d_in[1];
    const float* A  = (const float*)d_in[2];
    const float* W[4] = { (const float*)d_in[3], (const float*)d_in[5],
                          (const float*)d_in[7], (const float*)d_in[9] };
    const float* B[4] = { (const float*)d_in[4], (const float*)d_in[6],
                          (const float*)d_in[8], (const float*)d_in[10] };
    float* out = (float*)d_out;

    float *r0, *r1;
    __nv_bfloat16 *yhi, *ylo, *whi, *wlo;
    cudaGetSymbolAddress((void**)&r0,  g_r0);
    cudaGetSymbolAddress((void**)&r1,  g_r1);
    cudaGetSymbolAddress((void**)&yhi, g_yhi);
    cudaGetSymbolAddress((void**)&ylo, g_ylo);
    cudaGetSymbolAddress((void**)&whi, g_whi);
    cudaGetSymbolAddress((void**)&wlo, g_wlo);

    cudaFuncSetAttribute(gemm_kernel,
                         cudaFuncAttributeMaxDynamicSharedMemorySize, SM_TOTAL);

    wsplit_kernel<<<1024, 256>>>(W[0], W[1], W[2], W[3], whi, wlo);

    dim3 ggrid(13, 2, NN);
    const float* cur = x;       int curs = 25;
    float* nxt[4]   = { r0, r1, r0, out };
    int    nxts[4]  = { 26, 26, 26, 25 };

    for (int l = 0; l < 4; l++) {
        mix_kernel<<<NROWS / 256, 256>>>(cur, A, yhi, ylo, curs);
        gemm_kernel<<<ggrid, 256, SM_TOTAL>>>(yhi, ylo,
                                              whi + (size_t)l * CC * CC,
                                              wlo + (size_t)l * CC * CC,
                                              B[l], cur, nxt[l], curs, nxts[l]);
        cur = nxt[l]; curs = nxts[l];
    }
}